// round 12
// baseline (speedup 1.0000x reference)
#include <cuda_runtime.h>
#include <cuda_fp16.h>
#include <stdint.h>

// ---------------- problem constants ----------------
#define N_USERS  50000
#define N_ITEMS  100000
#define N_NODES  (N_USERS + N_ITEMS)     // 150000
#define N_EDGES  2400000
#define DIM      64
#define BATCH    4096

#define TOTAL    (N_NODES * DIM)         // 9,600,000 floats
#define TOT8     (TOTAL / 8)             // uint4-of-half count per buffer

#define SCAN_B   1024
#define NBLK     ((N_NODES + SCAN_B - 1) / SCAN_B)   // 147

#define FLG_AGG  (1ULL << 62)
#define FLG_INC  (2ULL << 62)

#define T           256
#define HIST_BLOCKS (((N_EDGES / 4) + T - 1) / T)      // 2344
#define SCT_BLOCKS  HIST_BLOCKS
#define CVT_BLOCKS  ((TOT8 + T - 1) / T)               // 4688

// ---------------- scratch (device globals; zero-initialized at load) ----------------
// TWO state buffers (fp16): bufA = emb -> layer-2 output; bufB = layer-1 output.
__device__ uint4 g_bufA[TOT8];
__device__ uint4 g_bufB[TOT8];

__device__ int2  g_edge  [N_EDGES];      // packed (src, val_fp32) grouped by dst
__device__ int   g_cnt   [N_NODES];      // degree counter; countdown scatter returns it to 0
__device__ int   g_rowptr[N_NODES + 1];
__device__ unsigned long long g_part[NBLK];   // lookback scan state (reset every run)

// ---------------- helpers ----------------
__device__ __forceinline__ unsigned pack_h2(float a, float b) {
    __half2 h = __floats2half2_rn(a, b);
    return *reinterpret_cast<unsigned*>(&h);
}
__device__ __forceinline__ float2 unpack_h2(unsigned u) {
    return __half22float2(*reinterpret_cast<__half2*>(&u));
}
__device__ __forceinline__ __half2 as_h2(unsigned u) {
    return *reinterpret_cast<__half2*>(&u);
}

// ---------------- launch 1: histogram (+ g_part reset) ----------------------------
__global__ void hist_kernel(const int* __restrict__ dst) {
    int t = blockIdx.x * blockDim.x + threadIdx.x;
    if (t < NBLK) g_part[t] = 0ULL;                  // reset lookback state
    if (t * 4 >= N_EDGES) return;
    int4 d = reinterpret_cast<const int4*>(dst)[t];
    atomicAdd(&g_cnt[d.x], 1);
    atomicAdd(&g_cnt[d.y], 1);
    atomicAdd(&g_cnt[d.z], 1);
    atomicAdd(&g_cnt[d.w], 1);
}

// ---------------- launch 2: one-pass decoupled-lookback exclusive scan ------------
__global__ void scan_kernel() {
    __shared__ int warp_tot[32];
    __shared__ int s_prefix;
    __shared__ int s_total;
    int b    = blockIdx.x;
    int gid  = b * SCAN_B + threadIdx.x;
    int lane = threadIdx.x & 31;
    int wid  = threadIdx.x >> 5;

    int v = (gid < N_NODES) ? g_cnt[gid] : 0;
    int inc = v;
    #pragma unroll
    for (int off = 1; off < 32; off <<= 1) {
        int t = __shfl_up_sync(0xFFFFFFFFu, inc, off);
        if (lane >= off) inc += t;
    }
    if (lane == 31) warp_tot[wid] = inc;
    __syncthreads();
    if (wid == 0) {
        int t = warp_tot[lane];
        int s = t;
        #pragma unroll
        for (int off = 1; off < 32; off <<= 1) {
            int u = __shfl_up_sync(0xFFFFFFFFu, s, off);
            if (lane >= off) s += u;
        }
        warp_tot[lane] = s - t;
    }
    __syncthreads();
    int ex = inc - v + warp_tot[wid];                   // exclusive within block
    if (threadIdx.x == SCAN_B - 1) s_total = ex + v;
    __syncthreads();
    int total = s_total;

    if (threadIdx.x == 0) {
        if (b == 0) {
            atomicExch(&g_part[0], FLG_INC | (unsigned long long)(unsigned)total);
            s_prefix = 0;
        } else {
            atomicExch(&g_part[b], FLG_AGG | (unsigned long long)(unsigned)total);
            int run = 0;
            int p = b - 1;
            while (true) {
                unsigned long long st  = atomicAdd(&g_part[p], 0ULL);
                unsigned long long flg = st & (3ULL << 62);
                if (flg == FLG_INC) { run += (int)(unsigned)st; break; }
                if (flg == FLG_AGG) { run += (int)(unsigned)st; p--; }
            }
            atomicExch(&g_part[b],
                       FLG_INC | (unsigned long long)(unsigned)(run + total));
            s_prefix = run;
        }
    }
    __syncthreads();
    if (gid < N_NODES) g_rowptr[gid] = ex + s_prefix;
    if (b == NBLK - 1 && threadIdx.x == 0) g_rowptr[N_NODES] = N_EDGES;
}

// ---------------- launch 3: scatter ∥ convert (disjoint block ranges) -------------
__global__ void sct_cvt_kernel(const int* __restrict__ src,
                               const int* __restrict__ dst,
                               const float* __restrict__ vals,
                               const float* __restrict__ eu,
                               const float* __restrict__ ei) {
    if (blockIdx.x < SCT_BLOCKS) {
        int t = blockIdx.x * T + threadIdx.x;
        if (t * 4 >= N_EDGES) return;
        int4   s4 = reinterpret_cast<const int4*>(src)[t];
        int4   d4 = reinterpret_cast<const int4*>(dst)[t];
        float4 v4 = reinterpret_cast<const float4*>(vals)[t];
        int p;
        p = g_rowptr[d4.x] + atomicSub(&g_cnt[d4.x], 1) - 1;
        g_edge[p] = make_int2(s4.x, __float_as_int(v4.x));
        p = g_rowptr[d4.y] + atomicSub(&g_cnt[d4.y], 1) - 1;
        g_edge[p] = make_int2(s4.y, __float_as_int(v4.y));
        p = g_rowptr[d4.z] + atomicSub(&g_cnt[d4.z], 1) - 1;
        g_edge[p] = make_int2(s4.z, __float_as_int(v4.z));
        p = g_rowptr[d4.w] + atomicSub(&g_cnt[d4.w], 1) - 1;
        g_edge[p] = make_int2(s4.w, __float_as_int(v4.w));
    } else {
        int idx = (blockIdx.x - SCT_BLOCKS) * T + threadIdx.x;   // uint4 index
        if (idx >= TOT8) return;
        const int nu8 = (N_USERS * DIM) / 8;
        const float4* s;
        if (idx < nu8) s = reinterpret_cast<const float4*>(eu) + (size_t)idx * 2;
        else           s = reinterpret_cast<const float4*>(ei) + (size_t)(idx - nu8) * 2;
        float4 a = s[0], b = s[1];
        uint4 o;
        o.x = pack_h2(a.x, a.y);
        o.y = pack_h2(a.z, a.w);
        o.z = pack_h2(b.x, b.y);
        o.w = pack_h2(b.z, b.w);
        g_bufA[idx] = o;
    }
}

// ---------------- launches 4,5: gather SpMM (HFMA2 accumulation) -----------------
// one warp per dst node; c = lane&7 -> 16B chunk of row; slot = lane>>3 in [0,4)
// -> edge stream. Inner loop is packed half2 FMA (4 HFMA2 per chunk per edge);
// each slot stream sums only ~deg/4 fp16 terms before the cross-slot reduction
// happens in fp32.
__global__ void __launch_bounds__(256) spmm_half_kernel(
        const uint4* __restrict__ x, uint4* __restrict__ y) {
    int node = blockIdx.x * (blockDim.x >> 5) + (threadIdx.x >> 5);
    if (node >= N_NODES) return;
    int lane = threadIdx.x & 31;
    int c    = lane & 7;
    int slot = lane >> 3;

    int beg = g_rowptr[node];
    int end = g_rowptr[node + 1];

    __half2 acc[4];
    #pragma unroll
    for (int k = 0; k < 4; k++) acc[k] = __float2half2_rn(0.f);

    int j = beg + slot;
    for (; j + 4 < end; j += 8) {
        int2  e0 = g_edge[j];
        int2  e1 = g_edge[j + 4];
        uint4 h0 = x[e0.x * 8 + c];
        uint4 h1 = x[e1.x * 8 + c];
        __half2 v0 = __float2half2_rn(__int_as_float(e0.y));
        __half2 v1 = __float2half2_rn(__int_as_float(e1.y));
        acc[0] = __hfma2(v0, as_h2(h0.x), acc[0]);
        acc[1] = __hfma2(v0, as_h2(h0.y), acc[1]);
        acc[2] = __hfma2(v0, as_h2(h0.z), acc[2]);
        acc[3] = __hfma2(v0, as_h2(h0.w), acc[3]);
        acc[0] = __hfma2(v1, as_h2(h1.x), acc[0]);
        acc[1] = __hfma2(v1, as_h2(h1.y), acc[1]);
        acc[2] = __hfma2(v1, as_h2(h1.z), acc[2]);
        acc[3] = __hfma2(v1, as_h2(h1.w), acc[3]);
    }
    if (j < end) {
        int2  e0 = g_edge[j];
        uint4 h0 = x[e0.x * 8 + c];
        __half2 v0 = __float2half2_rn(__int_as_float(e0.y));
        acc[0] = __hfma2(v0, as_h2(h0.x), acc[0]);
        acc[1] = __hfma2(v0, as_h2(h0.y), acc[1]);
        acc[2] = __hfma2(v0, as_h2(h0.z), acc[2]);
        acc[3] = __hfma2(v0, as_h2(h0.w), acc[3]);
    }

    // convert to fp32 and combine the 4 slot groups in fp32
    float a[8];
    #pragma unroll
    for (int k = 0; k < 4; k++) {
        float2 f = __half22float2(acc[k]);
        a[2 * k]     = f.x;
        a[2 * k + 1] = f.y;
    }
    #pragma unroll
    for (int k = 0; k < 8; k++) {
        a[k] += __shfl_xor_sync(0xFFFFFFFFu, a[k], 8);
        a[k] += __shfl_xor_sync(0xFFFFFFFFu, a[k], 16);
    }
    if (slot == 0) {
        uint4 o;
        o.x = pack_h2(a[0], a[1]);
        o.y = pack_h2(a[2], a[3]);
        o.z = pack_h2(a[4], a[5]);
        o.w = pack_h2(a[6], a[7]);
        y[node * 8 + c] = o;
    }
}

// ---------------- launch 6: fused layer-3 gather + dot (fp32 accumulate) ---------
__device__ __forceinline__ void gather3_chunk(const uint4* __restrict__ x2,
                                              int node, int c, int slot,
                                              float (&g)[8]) {
    int beg = g_rowptr[node];
    int end = g_rowptr[node + 1];
    #pragma unroll
    for (int k = 0; k < 8; k++) g[k] = 0.f;
    for (int j = beg + slot; j < end; j += 4) {
        int2  ed = g_edge[j];
        float v  = __int_as_float(ed.y);
        uint4 h  = x2[ed.x * 8 + c];
        float2 f;
        f = unpack_h2(h.x); g[0] += v * f.x; g[1] += v * f.y;
        f = unpack_h2(h.y); g[2] += v * f.x; g[3] += v * f.y;
        f = unpack_h2(h.z); g[4] += v * f.x; g[5] += v * f.y;
        f = unpack_h2(h.w); g[6] += v * f.x; g[7] += v * f.y;
    }
    #pragma unroll
    for (int k = 0; k < 8; k++) {
        g[k] += __shfl_xor_sync(0xFFFFFFFFu, g[k], 8);
        g[k] += __shfl_xor_sync(0xFFFFFFFFu, g[k], 16);
    }
}

// x1 = g_bufB (layer-1 output), x2 = g_bufA (layer-2 output)
__global__ void dot_fused_kernel(const int* __restrict__ users,
                                 const int* __restrict__ items,
                                 const float* __restrict__ eu,
                                 const float* __restrict__ ei,
                                 float* __restrict__ out) {
    int b = blockIdx.x * (blockDim.x >> 5) + (threadIdx.x >> 5);
    if (b >= BATCH) return;
    int lane = threadIdx.x & 31;
    int c    = lane & 7;
    int slot = lane >> 3;

    int u  = users[b];
    int im = items[b];
    int ni = N_USERS + im;

    float gu[8], gi[8];
    gather3_chunk(g_bufA, u,  c, slot, gu);
    gather3_chunk(g_bufA, ni, c, slot, gi);

    const float4* pu4 = reinterpret_cast<const float4*>(eu + u  * DIM + c * 8);
    const float4* pi4 = reinterpret_cast<const float4*>(ei + im * DIM + c * 8);
    float4 bu0 = pu4[0], bu1 = pu4[1];
    float4 bi0 = pi4[0], bi1 = pi4[1];

    uint4 u1h = g_bufB[u  * 8 + c], u2h = g_bufA[u  * 8 + c];
    uint4 i1h = g_bufB[ni * 8 + c], i2h = g_bufA[ni * 8 + c];

    float ru[8], ri[8];
    {
        float2 t;
        t = unpack_h2(u1h.x); ru[0] = bu0.x + t.x; ru[1] = bu0.y + t.y;
        t = unpack_h2(u1h.y); ru[2] = bu0.z + t.x; ru[3] = bu0.w + t.y;
        t = unpack_h2(u1h.z); ru[4] = bu1.x + t.x; ru[5] = bu1.y + t.y;
        t = unpack_h2(u1h.w); ru[6] = bu1.z + t.x; ru[7] = bu1.w + t.y;
        t = unpack_h2(u2h.x); ru[0] += t.x; ru[1] += t.y;
        t = unpack_h2(u2h.y); ru[2] += t.x; ru[3] += t.y;
        t = unpack_h2(u2h.z); ru[4] += t.x; ru[5] += t.y;
        t = unpack_h2(u2h.w); ru[6] += t.x; ru[7] += t.y;

        t = unpack_h2(i1h.x); ri[0] = bi0.x + t.x; ri[1] = bi0.y + t.y;
        t = unpack_h2(i1h.y); ri[2] = bi0.z + t.x; ri[3] = bi0.w + t.y;
        t = unpack_h2(i1h.z); ri[4] = bi1.x + t.x; ri[5] = bi1.y + t.y;
        t = unpack_h2(i1h.w); ri[6] = bi1.z + t.x; ri[7] = bi1.w + t.y;
        t = unpack_h2(i2h.x); ri[0] += t.x; ri[1] += t.y;
        t = unpack_h2(i2h.y); ri[2] += t.x; ri[3] += t.y;
        t = unpack_h2(i2h.z); ri[4] += t.x; ri[5] += t.y;
        t = unpack_h2(i2h.w); ri[6] += t.x; ri[7] += t.y;
    }

    float p = 0.f;
    #pragma unroll
    for (int k = 0; k < 8; k++)
        p += (ru[k] + gu[k]) * (ri[k] + gi[k]);

    p += __shfl_xor_sync(0xFFFFFFFFu, p, 1);
    p += __shfl_xor_sync(0xFFFFFFFFu, p, 2);
    p += __shfl_xor_sync(0xFFFFFFFFu, p, 4);

    if (lane == 0)
        out[b] = p * (1.0f / 16.0f);     // (1/4)^2 mean-pool factors
}

// ---------------- launch ----------------
extern "C" void kernel_launch(void* const* d_in, const int* in_sizes, int n_in,
                              void* d_out, int out_size) {
    (void)in_sizes; (void)n_in; (void)out_size;
    const float* emb_user = (const float*)d_in[0];
    const float* emb_item = (const float*)d_in[1];
    const float* vals     = (const float*)d_in[2];
    const int*   src      = (const int*)  d_in[3];
    const int*   dst      = (const int*)  d_in[4];
    const int*   users    = (const int*)  d_in[5];
    const int*   items    = (const int*)  d_in[6];
    float* out = (float*)d_out;

    uint4 *bA, *bB;
    cudaGetSymbolAddress((void**)&bA, g_bufA);
    cudaGetSymbolAddress((void**)&bB, g_bufB);

    // 1: histogram (+ g_part reset)
    hist_kernel<<<HIST_BLOCKS, T>>>(dst);
    // 2: one-pass scan -> rowptr
    scan_kernel<<<NBLK, SCAN_B>>>();
    // 3: scatter ∥ convert (scatter leaves g_cnt zeroed for next replay)
    sct_cvt_kernel<<<SCT_BLOCKS + CVT_BLOCKS, T>>>(src, dst, vals,
                                                   emb_user, emb_item);

    // 4,5: propagation (fp16 state, HFMA2 accumulate), two-buffer ping-pong
    const int wpb = T / 32;
    const int grid_spmm = (N_NODES + wpb - 1) / wpb;
    spmm_half_kernel<<<grid_spmm, T>>>(bA, bB);   // layer 1: A -> B
    spmm_half_kernel<<<grid_spmm, T>>>(bB, bA);   // layer 2: B -> A (emb dead)

    // 6: layer 3 fused with batched dot (x1 = B, x2 = A)
    const int grid_dot = (BATCH + wpb - 1) / wpb;
    dot_fused_kernel<<<grid_dot, T>>>(users, items, emb_user, emb_item, out);
}

// round 13
// speedup vs baseline: 1.0733x; 1.0733x over previous
#include <cuda_runtime.h>
#include <cuda_fp16.h>
#include <stdint.h>

// ---------------- problem constants ----------------
#define N_USERS  50000
#define N_ITEMS  100000
#define N_NODES  (N_USERS + N_ITEMS)     // 150000
#define N_EDGES  2400000
#define DIM      64
#define BATCH    4096

#define TOTAL    (N_NODES * DIM)         // 9,600,000 floats
#define TOT8     (TOTAL / 8)             // uint4-of-half count per buffer

#define SCAN_B   1024
#define NBLK     ((N_NODES + SCAN_B - 1) / SCAN_B)   // 147

#define FLG_AGG  (1ULL << 62)
#define FLG_INC  (2ULL << 62)

#define T           256
#define HIST_BLOCKS (((N_EDGES / 4) + T - 1) / T)      // 2344
#define SCT_BLOCKS  HIST_BLOCKS
#define CVT_BLOCKS  ((TOT8 + T - 1) / T)               // 4688

// ---------------- scratch (device globals; zero-initialized at load) ----------------
// TWO state buffers (fp16): bufA = emb -> layer-2 output; bufB = layer-1 output.
__device__ uint4 g_bufA[TOT8];
__device__ uint4 g_bufB[TOT8];

__device__ int2  g_edge  [N_EDGES];      // packed (src, val_fp32) grouped by dst
__device__ int   g_cnt   [N_NODES];      // degree counter; countdown scatter returns it to 0
__device__ int   g_rowptr[N_NODES + 1];
__device__ unsigned long long g_part[NBLK];   // lookback scan state (reset every run)

// ---------------- helpers ----------------
__device__ __forceinline__ unsigned pack_h2(float a, float b) {
    __half2 h = __floats2half2_rn(a, b);
    return *reinterpret_cast<unsigned*>(&h);
}
__device__ __forceinline__ float2 unpack_h2(unsigned u) {
    return __half22float2(*reinterpret_cast<__half2*>(&u));
}
__device__ __forceinline__ unsigned f32_to_h2(float f) {
    __half2 h = __float2half2_rn(f);
    return *reinterpret_cast<unsigned*>(&h);
}
__device__ __forceinline__ void hfma2_asm(unsigned& acc, unsigned v, unsigned h) {
    asm("fma.rn.f16x2 %0, %1, %2, %0;" : "+r"(acc) : "r"(v), "r"(h));
}

// ---------------- launch 1: histogram (+ g_part reset) ----------------------------
__global__ void hist_kernel(const int* __restrict__ dst) {
    int t = blockIdx.x * blockDim.x + threadIdx.x;
    if (t < NBLK) g_part[t] = 0ULL;                  // reset lookback state
    if (t * 4 >= N_EDGES) return;
    int4 d = reinterpret_cast<const int4*>(dst)[t];
    atomicAdd(&g_cnt[d.x], 1);
    atomicAdd(&g_cnt[d.y], 1);
    atomicAdd(&g_cnt[d.z], 1);
    atomicAdd(&g_cnt[d.w], 1);
}

// ---------------- launch 2: one-pass decoupled-lookback exclusive scan ------------
__global__ void scan_kernel() {
    __shared__ int warp_tot[32];
    __shared__ int s_prefix;
    __shared__ int s_total;
    int b    = blockIdx.x;
    int gid  = b * SCAN_B + threadIdx.x;
    int lane = threadIdx.x & 31;
    int wid  = threadIdx.x >> 5;

    int v = (gid < N_NODES) ? g_cnt[gid] : 0;
    int inc = v;
    #pragma unroll
    for (int off = 1; off < 32; off <<= 1) {
        int t = __shfl_up_sync(0xFFFFFFFFu, inc, off);
        if (lane >= off) inc += t;
    }
    if (lane == 31) warp_tot[wid] = inc;
    __syncthreads();
    if (wid == 0) {
        int t = warp_tot[lane];
        int s = t;
        #pragma unroll
        for (int off = 1; off < 32; off <<= 1) {
            int u = __shfl_up_sync(0xFFFFFFFFu, s, off);
            if (lane >= off) s += u;
        }
        warp_tot[lane] = s - t;
    }
    __syncthreads();
    int ex = inc - v + warp_tot[wid];                   // exclusive within block
    if (threadIdx.x == SCAN_B - 1) s_total = ex + v;
    __syncthreads();
    int total = s_total;

    if (threadIdx.x == 0) {
        if (b == 0) {
            atomicExch(&g_part[0], FLG_INC | (unsigned long long)(unsigned)total);
            s_prefix = 0;
        } else {
            atomicExch(&g_part[b], FLG_AGG | (unsigned long long)(unsigned)total);
            int run = 0;
            int p = b - 1;
            while (true) {
                unsigned long long st  = atomicAdd(&g_part[p], 0ULL);
                unsigned long long flg = st & (3ULL << 62);
                if (flg == FLG_INC) { run += (int)(unsigned)st; break; }
                if (flg == FLG_AGG) { run += (int)(unsigned)st; p--; }
            }
            atomicExch(&g_part[b],
                       FLG_INC | (unsigned long long)(unsigned)(run + total));
            s_prefix = run;
        }
    }
    __syncthreads();
    if (gid < N_NODES) g_rowptr[gid] = ex + s_prefix;
    if (b == NBLK - 1 && threadIdx.x == 0) g_rowptr[N_NODES] = N_EDGES;
}

// ---------------- launch 3: scatter ∥ convert (disjoint block ranges) -------------
__global__ void sct_cvt_kernel(const int* __restrict__ src,
                               const int* __restrict__ dst,
                               const float* __restrict__ vals,
                               const float* __restrict__ eu,
                               const float* __restrict__ ei) {
    if (blockIdx.x < SCT_BLOCKS) {
        int t = blockIdx.x * T + threadIdx.x;
        if (t * 4 >= N_EDGES) return;
        int4   s4 = reinterpret_cast<const int4*>(src)[t];
        int4   d4 = reinterpret_cast<const int4*>(dst)[t];
        float4 v4 = reinterpret_cast<const float4*>(vals)[t];
        int p;
        p = g_rowptr[d4.x] + atomicSub(&g_cnt[d4.x], 1) - 1;
        g_edge[p] = make_int2(s4.x, __float_as_int(v4.x));
        p = g_rowptr[d4.y] + atomicSub(&g_cnt[d4.y], 1) - 1;
        g_edge[p] = make_int2(s4.y, __float_as_int(v4.y));
        p = g_rowptr[d4.z] + atomicSub(&g_cnt[d4.z], 1) - 1;
        g_edge[p] = make_int2(s4.z, __float_as_int(v4.z));
        p = g_rowptr[d4.w] + atomicSub(&g_cnt[d4.w], 1) - 1;
        g_edge[p] = make_int2(s4.w, __float_as_int(v4.w));
    } else {
        int idx = (blockIdx.x - SCT_BLOCKS) * T + threadIdx.x;   // uint4 index
        if (idx >= TOT8) return;
        const int nu8 = (N_USERS * DIM) / 8;
        const float4* s;
        if (idx < nu8) s = reinterpret_cast<const float4*>(eu) + (size_t)idx * 2;
        else           s = reinterpret_cast<const float4*>(ei) + (size_t)(idx - nu8) * 2;
        float4 a = s[0], b = s[1];
        uint4 o;
        o.x = pack_h2(a.x, a.y);
        o.y = pack_h2(a.z, a.w);
        o.z = pack_h2(b.x, b.y);
        o.w = pack_h2(b.z, b.w);
        g_bufA[idx] = o;
    }
}

// ---------------- launches 4,5: gather SpMM (asm HFMA2, forced occupancy) --------
// one warp per dst node; c = lane&7 -> 16B chunk of row; slot = lane>>3 in [0,4)
// -> edge stream. Packed fp16 FMA on unsigned regs (4 HFMA2 per chunk per edge);
// each slot stream sums only ~deg/4 fp16 terms, cross-slot reduction in fp32.
// __launch_bounds__(256, 8) caps regs at 32 -> 8 blocks/SM.
__global__ void __launch_bounds__(256, 8) spmm_half_kernel(
        const uint4* __restrict__ x, uint4* __restrict__ y) {
    int node = blockIdx.x * (blockDim.x >> 5) + (threadIdx.x >> 5);
    if (node >= N_NODES) return;
    int lane = threadIdx.x & 31;
    int c    = lane & 7;
    int slot = lane >> 3;

    int beg = g_rowptr[node];
    int end = g_rowptr[node + 1];

    unsigned acc0 = 0u, acc1 = 0u, acc2 = 0u, acc3 = 0u;   // half2 +0.0 pairs

    int j = beg + slot;
    for (; j + 4 < end; j += 8) {
        int2  e0 = g_edge[j];
        int2  e1 = g_edge[j + 4];
        uint4 h0 = x[e0.x * 8 + c];
        uint4 h1 = x[e1.x * 8 + c];
        unsigned v0 = f32_to_h2(__int_as_float(e0.y));
        unsigned v1 = f32_to_h2(__int_as_float(e1.y));
        hfma2_asm(acc0, v0, h0.x);
        hfma2_asm(acc1, v0, h0.y);
        hfma2_asm(acc2, v0, h0.z);
        hfma2_asm(acc3, v0, h0.w);
        hfma2_asm(acc0, v1, h1.x);
        hfma2_asm(acc1, v1, h1.y);
        hfma2_asm(acc2, v1, h1.z);
        hfma2_asm(acc3, v1, h1.w);
    }
    if (j < end) {
        int2  e0 = g_edge[j];
        uint4 h0 = x[e0.x * 8 + c];
        unsigned v0 = f32_to_h2(__int_as_float(e0.y));
        hfma2_asm(acc0, v0, h0.x);
        hfma2_asm(acc1, v0, h0.y);
        hfma2_asm(acc2, v0, h0.z);
        hfma2_asm(acc3, v0, h0.w);
    }

    // convert to fp32 and combine the 4 slot groups in fp32
    float a[8];
    { float2 f = unpack_h2(acc0); a[0] = f.x; a[1] = f.y; }
    { float2 f = unpack_h2(acc1); a[2] = f.x; a[3] = f.y; }
    { float2 f = unpack_h2(acc2); a[4] = f.x; a[5] = f.y; }
    { float2 f = unpack_h2(acc3); a[6] = f.x; a[7] = f.y; }
    #pragma unroll
    for (int k = 0; k < 8; k++) {
        a[k] += __shfl_xor_sync(0xFFFFFFFFu, a[k], 8);
        a[k] += __shfl_xor_sync(0xFFFFFFFFu, a[k], 16);
    }
    if (slot == 0) {
        uint4 o;
        o.x = pack_h2(a[0], a[1]);
        o.y = pack_h2(a[2], a[3]);
        o.z = pack_h2(a[4], a[5]);
        o.w = pack_h2(a[6], a[7]);
        y[node * 8 + c] = o;
    }
}

// ---------------- launch 6: fused layer-3 gather + dot (fp32 accumulate) ---------
__device__ __forceinline__ void gather3_chunk(const uint4* __restrict__ x2,
                                              int node, int c, int slot,
                                              float (&g)[8]) {
    int beg = g_rowptr[node];
    int end = g_rowptr[node + 1];
    #pragma unroll
    for (int k = 0; k < 8; k++) g[k] = 0.f;
    for (int j = beg + slot; j < end; j += 4) {
        int2  ed = g_edge[j];
        float v  = __int_as_float(ed.y);
        uint4 h  = x2[ed.x * 8 + c];
        float2 f;
        f = unpack_h2(h.x); g[0] += v * f.x; g[1] += v * f.y;
        f = unpack_h2(h.y); g[2] += v * f.x; g[3] += v * f.y;
        f = unpack_h2(h.z); g[4] += v * f.x; g[5] += v * f.y;
        f = unpack_h2(h.w); g[6] += v * f.x; g[7] += v * f.y;
    }
    #pragma unroll
    for (int k = 0; k < 8; k++) {
        g[k] += __shfl_xor_sync(0xFFFFFFFFu, g[k], 8);
        g[k] += __shfl_xor_sync(0xFFFFFFFFu, g[k], 16);
    }
}

// x1 = g_bufB (layer-1 output), x2 = g_bufA (layer-2 output)
__global__ void dot_fused_kernel(const int* __restrict__ users,
                                 const int* __restrict__ items,
                                 const float* __restrict__ eu,
                                 const float* __restrict__ ei,
                                 float* __restrict__ out) {
    int b = blockIdx.x * (blockDim.x >> 5) + (threadIdx.x >> 5);
    if (b >= BATCH) return;
    int lane = threadIdx.x & 31;
    int c    = lane & 7;
    int slot = lane >> 3;

    int u  = users[b];
    int im = items[b];
    int ni = N_USERS + im;

    float gu[8], gi[8];
    gather3_chunk(g_bufA, u,  c, slot, gu);
    gather3_chunk(g_bufA, ni, c, slot, gi);

    const float4* pu4 = reinterpret_cast<const float4*>(eu + u  * DIM + c * 8);
    const float4* pi4 = reinterpret_cast<const float4*>(ei + im * DIM + c * 8);
    float4 bu0 = pu4[0], bu1 = pu4[1];
    float4 bi0 = pi4[0], bi1 = pi4[1];

    uint4 u1h = g_bufB[u  * 8 + c], u2h = g_bufA[u  * 8 + c];
    uint4 i1h = g_bufB[ni * 8 + c], i2h = g_bufA[ni * 8 + c];

    float ru[8], ri[8];
    {
        float2 t;
        t = unpack_h2(u1h.x); ru[0] = bu0.x + t.x; ru[1] = bu0.y + t.y;
        t = unpack_h2(u1h.y); ru[2] = bu0.z + t.x; ru[3] = bu0.w + t.y;
        t = unpack_h2(u1h.z); ru[4] = bu1.x + t.x; ru[5] = bu1.y + t.y;
        t = unpack_h2(u1h.w); ru[6] = bu1.z + t.x; ru[7] = bu1.w + t.y;
        t = unpack_h2(u2h.x); ru[0] += t.x; ru[1] += t.y;
        t = unpack_h2(u2h.y); ru[2] += t.x; ru[3] += t.y;
        t = unpack_h2(u2h.z); ru[4] += t.x; ru[5] += t.y;
        t = unpack_h2(u2h.w); ru[6] += t.x; ru[7] += t.y;

        t = unpack_h2(i1h.x); ri[0] = bi0.x + t.x; ri[1] = bi0.y + t.y;
        t = unpack_h2(i1h.y); ri[2] = bi0.z + t.x; ri[3] = bi0.w + t.y;
        t = unpack_h2(i1h.z); ri[4] = bi1.x + t.x; ri[5] = bi1.y + t.y;
        t = unpack_h2(i1h.w); ri[6] = bi1.z + t.x; ri[7] = bi1.w + t.y;
        t = unpack_h2(i2h.x); ri[0] += t.x; ri[1] += t.y;
        t = unpack_h2(i2h.y); ri[2] += t.x; ri[3] += t.y;
        t = unpack_h2(i2h.z); ri[4] += t.x; ri[5] += t.y;
        t = unpack_h2(i2h.w); ri[6] += t.x; ri[7] += t.y;
    }

    float p = 0.f;
    #pragma unroll
    for (int k = 0; k < 8; k++)
        p += (ru[k] + gu[k]) * (ri[k] + gi[k]);

    p += __shfl_xor_sync(0xFFFFFFFFu, p, 1);
    p += __shfl_xor_sync(0xFFFFFFFFu, p, 2);
    p += __shfl_xor_sync(0xFFFFFFFFu, p, 4);

    if (lane == 0)
        out[b] = p * (1.0f / 16.0f);     // (1/4)^2 mean-pool factors
}

// ---------------- launch ----------------
extern "C" void kernel_launch(void* const* d_in, const int* in_sizes, int n_in,
                              void* d_out, int out_size) {
    (void)in_sizes; (void)n_in; (void)out_size;
    const float* emb_user = (const float*)d_in[0];
    const float* emb_item = (const float*)d_in[1];
    const float* vals     = (const float*)d_in[2];
    const int*   src      = (const int*)  d_in[3];
    const int*   dst      = (const int*)  d_in[4];
    const int*   users    = (const int*)  d_in[5];
    const int*   items    = (const int*)  d_in[6];
    float* out = (float*)d_out;

    uint4 *bA, *bB;
    cudaGetSymbolAddress((void**)&bA, g_bufA);
    cudaGetSymbolAddress((void**)&bB, g_bufB);

    // 1: histogram (+ g_part reset)
    hist_kernel<<<HIST_BLOCKS, T>>>(dst);
    // 2: one-pass scan -> rowptr
    scan_kernel<<<NBLK, SCAN_B>>>();
    // 3: scatter ∥ convert (scatter leaves g_cnt zeroed for next replay)
    sct_cvt_kernel<<<SCT_BLOCKS + CVT_BLOCKS, T>>>(src, dst, vals,
                                                   emb_user, emb_item);

    // 4,5: propagation (fp16 state, asm HFMA2 accumulate), two-buffer ping-pong
    const int wpb = T / 32;
    const int grid_spmm = (N_NODES + wpb - 1) / wpb;
    spmm_half_kernel<<<grid_spmm, T>>>(bA, bB);   // layer 1: A -> B
    spmm_half_kernel<<<grid_spmm, T>>>(bB, bA);   // layer 2: B -> A (emb dead)

    // 6: layer 3 fused with batched dot (x1 = B, x2 = A)
    const int grid_dot = (BATCH + wpb - 1) / wpb;
    dot_fused_kernel<<<grid_dot, T>>>(users, items, emb_user, emb_item, out);
}